// round 15
// baseline (speedup 1.0000x reference)
#include <cuda_runtime.h>
#include <cuda_bf16.h>
#include <math.h>
#include <stdint.h>

#define PI_F 3.14159265358979323846f
// B=8, C=64, H=W=64, K=3, PD=576, SD=128, NQ=6, NL=2

__device__ float g_style[48];
// Pre-swizzled B tiles: [9 shifts][hi 72x64 | lo 72x64] bf16, [n][k] rows,
// 16B chunk index ^= (n&7). 18432 B per shift.
__device__ __align__(16) unsigned short g_Bt[9][9216];
// U bf16 planes: [z][s] rows of 64 bf16 (128B), chunk ^= (z&7).
// plane 0 = Ur hi, 1 = Ur lo, 2 = Ui hi, 3 = Ui lo.
__device__ __align__(16) unsigned short g_Ubf[4][4096];

__device__ __forceinline__ uint32_t smem_u32(const void* p) {
    uint32_t a;
    asm("{ .reg .u64 t; cvta.to.shared.u64 t, %1; cvt.u32.u64 %0, t; }" : "=r"(a) : "l"(p));
    return a;
}
__device__ __forceinline__ float fast_tanh(float x) {
    float t = __expf(-2.f * fabsf(x));
    float r = __fdividef(1.f - t, 1.f + t);
    return (x < 0.f) ? -r : r;
}

#define LDSM4(r, a) asm volatile("ldmatrix.sync.aligned.m8n8.x4.shared.b16 {%0,%1,%2,%3}, [%4];" \
    : "=r"((r)[0]), "=r"((r)[1]), "=r"((r)[2]), "=r"((r)[3]) : "r"(a))
#define LDSM2(r, a) asm volatile("ldmatrix.sync.aligned.m8n8.x2.shared.b16 {%0,%1}, [%2];" \
    : "=r"((r)[0]), "=r"((r)[1]) : "r"(a))
#define MMA(d, a, bb2) asm volatile( \
    "mma.sync.aligned.m16n8k16.row.col.f32.bf16.bf16.f32 " \
    "{%0,%1,%2,%3}, {%4,%5,%6,%7}, {%8,%9}, {%0,%1,%2,%3};" \
    : "+f"((d)[0]), "+f"((d)[1]), "+f"((d)[2]), "+f"((d)[3]) \
    : "r"((a)[0]), "r"((a)[1]), "r"((a)[2]), "r"((a)[3]), "r"((bb2)[0]), "r"((bb2)[1]))

__device__ __forceinline__ uint32_t pack_bf2(float a0, float a1) {
    __nv_bfloat16 h0 = __float2bfloat16(a0);
    __nv_bfloat16 h1 = __float2bfloat16(a1);
    return ((uint32_t)__bfloat16_as_ushort(h1) << 16) | __bfloat16_as_ushort(h0);
}

// ---------------------------------------------------------------------------
// Merged setup kernel: blocks 0..161 build B tiles (N=72); block 162 runs the
// quantum circuit (style angles + U bf16 planes), all-MUFU transcendentals.
// ---------------------------------------------------------------------------
__global__ void qcnn_setup_kernel(const float* __restrict__ style,
                                  const float* __restrict__ s2d_w,
                                  const float* __restrict__ s2d_b,
                                  const float* __restrict__ qcnn,
                                  const float* __restrict__ meas,
                                  const float* __restrict__ res_w,
                                  const float* __restrict__ dat_w)
{
    const int tid = threadIdx.x;  // 0..255

    if (blockIdx.x < 162) {
        int idx = blockIdx.x * 256 + tid;
        if (idx >= 41472) return;
        int shift = idx / 4608;
        int rem = idx - shift * 4608;
        int n = rem >> 6, c = rem & 63;
        int dy = shift / 3, dx = shift - dy * 3;
        int k = c * 9 + dy * 3 + dx;
        float wv = 0.f;
        if (n < 64) wv = res_w[n * 576 + k];
        else if (n < 70) wv = dat_w[(n - 64) * 576 + k];
        __nv_bfloat16 hi = __float2bfloat16(wv);
        __nv_bfloat16 lo = __float2bfloat16(wv - __bfloat162float(hi));
        int us = (n << 6) + (((c >> 3) ^ (n & 7)) << 3) + (c & 7);
        ((__nv_bfloat16*)g_Bt[shift])[us] = hi;
        ((__nv_bfloat16*)g_Bt[shift])[us + 4608] = lo;
        return;
    }

    // ---- block 162: quantum circuit ----
    if (tid < 48) {
        int b = tid / 6, j = tid - 6 * b;
        float acc = s2d_b[j];
        const float* sp = style + b * 128;
        const float* wp = s2d_w + j * 128;
        #pragma unroll 8
        for (int k = 0; k < 128; k++) acc += sp[k] * wp[k];
        g_style[tid] = fast_tanh(acc) * PI_F;
    }

    const int c = tid >> 2;
    const int q = tid & 3;
    const unsigned FULL = 0xffffffffu;
    float ur[16], ui[16];
    #pragma unroll
    for (int zz = 0; zz < 16; zz++) { ur[zz] = (c == q * 16 + zz) ? 1.f : 0.f; ui[zz] = 0.f; }

    for (int l = 0; l < 2; l++) {
        #pragma unroll
        for (int i = 0; i < 6; i++) {
            const int m = 1 << (5 - i);
            float thy = qcnn[((l * 6 + i) * 2 + 0) * 3 + 0];
            float thz = qcnn[((l * 6 + i) * 2 + 1) * 3 + 0];
            float cy, sy; __sincosf(0.5f * thy, &sy, &cy);
            if (m < 16) {
                #pragma unroll
                for (int zz = 0; zz < 16; zz++) {
                    if (!(zz & m)) {
                        int z1 = zz | m;
                        float r0 = ur[zz], i0 = ui[zz], r1 = ur[z1], i1 = ui[z1];
                        ur[zz] = cy * r0 - sy * r1;  ui[zz] = cy * i0 - sy * i1;
                        ur[z1] = sy * r0 + cy * r1;  ui[z1] = sy * i0 + cy * i1;
                    }
                }
            } else {
                const int lane = m >> 4;
                const int bitv = (q * 16 & m) ? 1 : 0;
                #pragma unroll
                for (int zz = 0; zz < 16; zz++) {
                    float pr = __shfl_xor_sync(FULL, ur[zz], lane);
                    float pi = __shfl_xor_sync(FULL, ui[zz], lane);
                    if (bitv == 0) { ur[zz] = cy * ur[zz] - sy * pr; ui[zz] = cy * ui[zz] - sy * pi; }
                    else           { ur[zz] = sy * pr + cy * ur[zz]; ui[zz] = sy * pi + cy * ui[zz]; }
                }
            }
            float cz, sz; __sincosf(0.5f * thz, &sz, &cz);
            #pragma unroll
            for (int zz = 0; zz < 16; zz++) {
                int z = q * 16 + zz;
                float ph = (z & m) ? sz : -sz;
                float r = ur[zz], im = ui[zz];
                ur[zz] = cz * r - ph * im;
                ui[zz] = cz * im + ph * r;
            }
        }
        #pragma unroll
        for (int i = 0; i < 6; i++) {
            const int mc = 1 << (5 - i);
            const int mt = 1 << (5 - ((i + 1) % 6));
            if (mt < 16) {
                #pragma unroll
                for (int zz = 0; zz < 16; zz++) {
                    int z = q * 16 + zz;
                    if ((z & mc) && !(zz & mt)) {
                        int z2 = zz | mt;
                        float tr = ur[zz], ti = ui[zz];
                        ur[zz] = ur[z2];  ui[zz] = ui[z2];
                        ur[z2] = tr;      ui[z2] = ti;
                    }
                }
            } else {
                const int lane = mt >> 4;
                #pragma unroll
                for (int zz = 0; zz < 16; zz++) {
                    float pr = __shfl_xor_sync(FULL, ur[zz], lane);
                    float pi = __shfl_xor_sync(FULL, ui[zz], lane);
                    int z = q * 16 + zz;
                    if (z & mc) { ur[zz] = pr; ui[zz] = pi; }
                }
            }
        }
    }
    #pragma unroll
    for (int i = 0; i < 6; i++) {
        const int m = 1 << (5 - i);
        float th = meas[i * 3 + 0], ph = meas[i * 3 + 1], la = meas[i * 3 + 2];
        float ct, st; __sincosf(0.5f * th, &st, &ct);
        float cl, sl; __sincosf(la, &sl, &cl);
        float cp, sp; __sincosf(ph, &sp, &cp);
        float cpl, spl; __sincosf(ph + la, &spl, &cpl);
        float u01r = -cl * st, u01i = -sl * st;
        float u10r =  cp * st, u10i =  sp * st;
        float u11r = cpl * ct, u11i = spl * ct;
        if (m < 16) {
            #pragma unroll
            for (int zz = 0; zz < 16; zz++) {
                if (!(zz & m)) {
                    int z1 = zz | m;
                    float r0 = ur[zz], i0 = ui[zz], r1 = ur[z1], i1 = ui[z1];
                    ur[zz] = ct * r0 + u01r * r1 - u01i * i1;
                    ui[zz] = ct * i0 + u01r * i1 + u01i * r1;
                    ur[z1] = u10r * r0 - u10i * i0 + u11r * r1 - u11i * i1;
                    ui[z1] = u10r * i0 + u10i * r0 + u11r * i1 + u11i * r1;
                }
            }
        } else {
            const int lane = m >> 4;
            const int bitv = (q * 16 & m) ? 1 : 0;
            #pragma unroll
            for (int zz = 0; zz < 16; zz++) {
                float pr = __shfl_xor_sync(FULL, ur[zz], lane);
                float pi = __shfl_xor_sync(FULL, ui[zz], lane);
                float r0 = ur[zz], i0 = ui[zz];
                if (bitv == 0) {
                    ur[zz] = ct * r0 + u01r * pr - u01i * pi;
                    ui[zz] = ct * i0 + u01r * pi + u01i * pr;
                } else {
                    ur[zz] = u10r * pr - u10i * pi + u11r * r0 - u11i * i0;
                    ui[zz] = u10r * pi + u10i * pr + u11r * i0 + u11i * r0;
                }
            }
        }
    }
    // bf16 split planes, transposed to [z][s], ldmatrix-swizzled
    #pragma unroll
    for (int zz = 0; zz < 16; zz++) {
        int z = q * 16 + zz;
        int us = (z << 6) + (((c >> 3) ^ (z & 7)) << 3) + (c & 7);
        __nv_bfloat16 rh = __float2bfloat16(ur[zz]);
        __nv_bfloat16 rl = __float2bfloat16(ur[zz] - __bfloat162float(rh));
        __nv_bfloat16 ih = __float2bfloat16(ui[zz]);
        __nv_bfloat16 il = __float2bfloat16(ui[zz] - __bfloat162float(ih));
        ((__nv_bfloat16*)g_Ubf[0])[us] = rh;
        ((__nv_bfloat16*)g_Ubf[1])[us] = rl;
        ((__nv_bfloat16*)g_Ubf[2])[us] = ih;
        ((__nv_bfloat16*)g_Ubf[3])[us] = il;
    }
}

// ---------------------------------------------------------------------------
// Conv inner loop, templated on number of n-tiles (5 for n0..39, 4 for 40..71)
// ---------------------------------------------------------------------------
template<int NT>
__device__ __forceinline__ void conv_k0_loop(
    uint32_t xb, uint32_t bb, uint32_t arow0, uint32_t arow1,
    uint32_t sw0, uint32_t sw1, uint32_t brow, int lane, float acc[2][5][4])
{
    const int bln = lane & 7;
    #pragma unroll
    for (int k0 = 0; k0 < 64; k0 += 16) {
        const uint32_t kca = (uint32_t)(k0 >> 3) + (uint32_t)(lane >> 4);
        uint32_t ah0[4], ah1[4], al0[4], al1[4], bf[5][2];
        uint32_t ad0 = xb + arow0 + ((kca ^ sw0) << 4);
        uint32_t ad1 = xb + arow1 + ((kca ^ sw1) << 4);
        LDSM4(ah0, ad0);
        LDSM4(ah1, ad1);
        LDSM4(al0, ad0 + 50688);   // OFF_XPL
        LDSM4(al1, ad1 + 50688);
        const uint32_t kcb = (uint32_t)(k0 >> 3) + (uint32_t)((lane >> 3) & 1);
        const uint32_t boff = bb + brow + ((kcb ^ (uint32_t)bln) << 4);
        #pragma unroll
        for (int nt = 0; nt < NT; nt++) LDSM2(bf[nt], boff + nt * 1024);
        #pragma unroll
        for (int nt = 0; nt < NT; nt++) { MMA(acc[0][nt], ah0, bf[nt]); MMA(acc[1][nt], ah1, bf[nt]); }
        #pragma unroll
        for (int nt = 0; nt < NT; nt++) { MMA(acc[0][nt], al0, bf[nt]); MMA(acc[1][nt], al1, bf[nt]); }
        #pragma unroll
        for (int nt = 0; nt < NT; nt++) LDSM2(bf[nt], boff + nt * 1024 + 9216);  // lo plane
        #pragma unroll
        for (int nt = 0; nt < NT; nt++) { MMA(acc[0][nt], ah0, bf[nt]); MMA(acc[1][nt], ah1, bf[nt]); }
    }
}

// ---------------------------------------------------------------------------
// Main kernel: 128 blocks x 640 threads (single wave). Block = (b, 4 rows).
// Conv (N=72) AND quantum matvec on mma.sync bf16 (3-term split each).
// SMEM (bytes):
//   XPH@0(50688) XPL@50688 | B0@101376(18432) B1@119808(18432)
//   UBF@147456 (32768)  e_s@180224(9216)
//   pw@189440(1536) pob@190976(256) prb@191232(256) pst@191488(64)
// Overlays (post-conv): conv_s@0 [4][64][80]f32 (81920),
//   a_hi@81920(32768), a_lo@114688(32768)
// ---------------------------------------------------------------------------
#define OFF_XPL  50688
#define OFF_B0   101376
#define B_STRIDE 18432
#define OFF_AHI  81920
#define OFF_ALO  114688
#define OFF_UBF  147456
#define OFF_ES   180224
#define OFF_PW   189440
#define OFF_POB  190976
#define OFF_PRB  191232
#define OFF_PST  191488
#define SMEM_BYTES 191552

__global__ __launch_bounds__(640, 1)
void qcnn_main_kernel(const float* __restrict__ x,
                      const float* __restrict__ dat_b,
                      const float* __restrict__ out_w,
                      const float* __restrict__ out_b,
                      const float* __restrict__ res_b,
                      float* __restrict__ out)
{
    extern __shared__ char smc[];
    const uint32_t smem_base = smem_u32(smc);
    float* conv_s = (float*)smc;                 // overlay post-GEMM
    float* e_s    = (float*)(smc + OFF_ES);
    float* pw     = (float*)(smc + OFF_PW);
    float* pob    = (float*)(smc + OFF_POB);
    float* prb    = (float*)(smc + OFF_PRB);
    float* pst    = (float*)(smc + OFF_PST);

    const int tid  = threadIdx.x;
    const int wid  = tid >> 5;
    const int lane = tid & 31;
    const int b    = blockIdx.x >> 4;
    const int h0   = (blockIdx.x & 15) << 2;

    // --- conflict-free transpose staging of input hi/lo planes ---
    for (int t = wid; t < 96; t += 20) {
        const int r  = t >> 4;
        const int wh = (t >> 3) & 1;
        const int ch = t & 7;
        const int w  = wh * 32 + lane;    // padded w index 0..63
        const int gw = w - 1;
        const int hr = h0 + r - 1;
        const bool ok = (hr >= 0) && (hr < 64) && (gw >= 0);
        float v[8];
        #pragma unroll
        for (int c2 = 0; c2 < 8; c2++) {
            int cc = ch * 8 + c2;
            v[c2] = ok ? x[(((b * 64 + cc) * 64 + hr) << 6) + gw] : 0.f;
        }
        uint4 hi4, lo4;
        uint32_t* hp = (uint32_t*)&hi4;
        uint32_t* lp = (uint32_t*)&lo4;
        #pragma unroll
        for (int j = 0; j < 4; j++) {
            float a0 = v[2 * j], a1 = v[2 * j + 1];
            __nv_bfloat16 h0b = __float2bfloat16(a0);
            __nv_bfloat16 h1b = __float2bfloat16(a1);
            hp[j] = ((uint32_t)__bfloat16_as_ushort(h1b) << 16) | __bfloat16_as_ushort(h0b);
            lp[j] = pack_bf2(a0 - __bfloat162float(h0b), a1 - __bfloat162float(h1b));
        }
        const int addr = ((r * 66 + w) << 7) + ((ch ^ (w & 7)) << 4);
        *(uint4*)(smc + addr) = hi4;
        *(uint4*)(smc + OFF_XPL + addr) = lo4;
    }
    // edge columns w=64 (gw=63) and w=65 (pad)
    if (tid < 96) {
        const int r  = tid >> 4;
        const int rem = tid & 15;
        const int ch = rem >> 1;
        const int w  = 64 + (rem & 1);
        const int hr = h0 + r - 1;
        const bool ok = (w == 64) && (hr >= 0) && (hr < 64);
        uint4 hi4, lo4;
        uint32_t* hp = (uint32_t*)&hi4;
        uint32_t* lp = (uint32_t*)&lo4;
        #pragma unroll
        for (int j = 0; j < 4; j++) {
            float a0 = 0.f, a1 = 0.f;
            if (ok) {
                int cc = ch * 8 + 2 * j;
                a0 = x[(((b * 64 + cc) * 64 + hr) << 6) + 63];
                a1 = x[(((b * 64 + cc + 1) * 64 + hr) << 6) + 63];
            }
            __nv_bfloat16 h0b = __float2bfloat16(a0);
            __nv_bfloat16 h1b = __float2bfloat16(a1);
            hp[j] = ((uint32_t)__bfloat16_as_ushort(h1b) << 16) | __bfloat16_as_ushort(h0b);
            lp[j] = pack_bf2(a0 - __bfloat162float(h0b), a1 - __bfloat162float(h1b));
        }
        const int addr = ((r * 66 + w) << 7) + ((ch ^ (w & 7)) << 4);
        *(uint4*)(smc + addr) = hi4;
        *(uint4*)(smc + OFF_XPL + addr) = lo4;
    }
    // --- B shift 0 into buf 0 ---
    {
        const uint4* src = (const uint4*)(g_Bt[0]);
        uint4* dst = (uint4*)(smc + OFF_B0);
        for (int i = tid; i < 1152; i += 640) dst[i] = src[i];
    }

    // compute-warp geometry (conv): SMSP-balanced asymmetric (mt, nh) mapping
    const int mt  = (wid & 3) | ((wid >> 3) << 2);
    const int nh  = (wid >> 2) & 1;
    const int o   = mt >> 1;
    const int w0c = (mt & 1) * 32;
    const int n0  = nh * 40;
    const int l15 = lane & 15;
    const int bln = lane & 7;
    const uint32_t brow = (uint32_t)(n0 + bln) * 128;

    float acc[2][5][4];
    #pragma unroll
    for (int m = 0; m < 2; m++)
        #pragma unroll
        for (int nt = 0; nt < 5; nt++)
            #pragma unroll
            for (int j = 0; j < 4; j++) acc[m][nt][j] = 0.f;

    for (int st = 0; st < 9; st++) {
        __syncthreads();
        const uint32_t bb = smem_base + OFF_B0 + (uint32_t)(st & 1) * B_STRIDE;
        if (wid < 16) {
            const int dy = st / 3, dx = st - dy * 3;
            const int srow = o + dy;
            const int ws0 = w0c + l15 + dx;
            const int ws1 = ws0 + 16;
            const uint32_t arow0 = (uint32_t)((srow * 66 + ws0) << 7);
            const uint32_t arow1 = (uint32_t)((srow * 66 + ws1) << 7);
            const uint32_t sw0 = ws0 & 7, sw1 = ws1 & 7;
            if (nh == 0)
                conv_k0_loop<5>(smem_base, bb, arow0, arow1, sw0, sw1, brow, lane, acc);
            else
                conv_k0_loop<4>(smem_base, bb, arow0, arow1, sw0, sw1, brow, lane, acc);
        } else {
            const int t2 = tid - 512;
            if (st < 8) {
                const uint4* src = (const uint4*)(g_Bt[st + 1]);
                uint4* dst = (uint4*)(smc + OFF_B0 + ((st + 1) & 1) * B_STRIDE);
                #pragma unroll
                for (int i = 0; i < 9; i++) dst[t2 + i * 128] = src[t2 + i * 128];
            }
            if (st == 0) {  // stage U planes + params
                for (int i = t2; i < 2048; i += 128)
                    ((uint4*)(smc + OFF_UBF))[i] = ((const uint4*)g_Ubf)[i];
                if (t2 < 96) ((uint4*)pw)[t2] = ((const uint4*)out_w)[t2];
                else if (t2 < 112) ((uint4*)pob)[t2 - 96] = ((const uint4*)out_b)[t2 - 96];
                else if (t2 < 128) ((uint4*)prb)[t2 - 112] = ((const uint4*)res_b)[t2 - 112];
                if (t2 < 6) { pst[t2] = g_style[b * 6 + t2]; pst[8 + t2] = dat_b[t2]; }
            }
        }
    }
    __syncthreads();   // all XP/B readers done -> safe to overlay conv_s

    // --- writeout conv acc -> conv_s [o][w][80] ---
    if (wid < 16) {
        const int r0 = lane >> 2;
        const int nc = n0 + (lane & 3) * 2;
        const int NTw = nh ? 4 : 5;
        #pragma unroll
        for (int m = 0; m < 2; m++) {
            const int wpx = w0c + m * 16 + r0;
            #pragma unroll 5
            for (int nt = 0; nt < NTw; nt++) {
                *(float2*)&conv_s[(o * 64 + wpx) * 80 + nc + nt * 8] =
                    make_float2(acc[m][nt][0], acc[m][nt][1]);
                *(float2*)&conv_s[(o * 64 + wpx + 8) * 80 + nc + nt * 8] =
                    make_float2(acc[m][nt][2], acc[m][nt][3]);
            }
        }
    }
    __syncthreads();

    // --- build product-state a as bf16 hi/lo planes [p(256)][s(64)] ---
    if (tid < 512) {
        const int q  = tid & 3;
        const int p2 = tid >> 2;
        #pragma unroll
        for (int it = 0; it < 2; it++) {
            const int p  = it * 128 + p2;
            const int o2 = p >> 6;
            const int wq = p & 63;
            float cc6[6], sn6[6];
            #pragma unroll
            for (int i = 0; i < 6; i++) {
                float pre = conv_s[(o2 * 64 + wq) * 80 + 64 + i];
                float th = fast_tanh(pre + pst[8 + i]) * PI_F + pst[i];
                __sincosf(0.5f * th, &sn6[i], &cc6[i]);
            }
            char* ah = smc + OFF_AHI + (p << 7);
            char* al = smc + OFF_ALO + (p << 7);
            const int psw = p & 7;
            #pragma unroll
            for (int zz = 0; zz < 16; zz += 2) {
                int s = q * 16 + zz;
                float a0 = ((s >> 5) & 1) ? sn6[0] : cc6[0];
                float a1 = (((s + 1) >> 5) & 1) ? sn6[0] : cc6[0];
                #pragma unroll
                for (int i = 1; i < 6; i++) {
                    a0 *= ((s >> (5 - i)) & 1) ? sn6[i] : cc6[i];
                    a1 *= (((s + 1) >> (5 - i)) & 1) ? sn6[i] : cc6[i];
                }
                __nv_bfloat16 h0 = __float2bfloat16(a0);
                __nv_bfloat16 h1 = __float2bfloat16(a1);
                uint32_t vh = ((uint32_t)__bfloat16_as_ushort(h1) << 16) | __bfloat16_as_ushort(h0);
                uint32_t vl = pack_bf2(a0 - __bfloat162float(h0), a1 - __bfloat162float(h1));
                int off = ((((s >> 3)) ^ psw) << 4) + ((s & 7) << 1);
                *(uint32_t*)(ah + off) = vh;
                *(uint32_t*)(al + off) = vl;
            }
        }
    }
    __syncthreads();

    // --- quantum matvec on HMMA: psi[256][64] = a @ U (re + im) ---
    if (wid < 16) {
        const uint32_t abase = smem_base + OFF_AHI;
        const uint32_t ubf   = smem_base + OFF_UBF;
        const int prow = (wid << 4) + l15;
        uint32_t ahf[4][4], alf[4][4];
        #pragma unroll
        for (int ks = 0; ks < 4; ks++) {
            uint32_t kca = (uint32_t)(ks * 2) + (uint32_t)(lane >> 4);
            uint32_t ad = abase + (prow << 7) + ((kca ^ (uint32_t)(l15 & 7)) << 4);
            LDSM4(ahf[ks], ad);
            LDSM4(alf[ks], ad + 32768);
        }
        const int bl2 = lane & 7;
        const int bsel = (lane >> 3) & 1;
        const float s3 = (lane & 2) ? -1.f : 1.f;
        const float s4 = (lane & 1) ? -1.f : 1.f;
        float eacc[2][6];
        #pragma unroll
        for (int r2 = 0; r2 < 2; r2++)
            #pragma unroll
            for (int i = 0; i < 6; i++) eacc[r2][i] = 0.f;

        #pragma unroll
        for (int hf = 0; hf < 2; hf++) {
            float ar[4][4], ai[4][4];
            #pragma unroll
            for (int nt = 0; nt < 4; nt++)
                #pragma unroll
                for (int j = 0; j < 4; j++) { ar[nt][j] = 0.f; ai[nt][j] = 0.f; }
            #pragma unroll
            for (int nt = 0; nt < 4; nt++) {
                const int z0 = hf * 32 + nt * 8;
                const uint32_t brow2 = ubf + (uint32_t)((z0 + bl2) << 7);
                #pragma unroll
                for (int ks = 0; ks < 4; ks++) {
                    uint32_t bh[2], blo[2];
                    uint32_t ba = brow2 + ((((uint32_t)(ks * 2 + bsel)) ^ (uint32_t)bl2) << 4);
                    LDSM2(bh, ba);                 // Ur hi
                    LDSM2(blo, ba + 8192);         // Ur lo
                    MMA(ar[nt], ahf[ks], bh);
                    MMA(ar[nt], ahf[ks], blo);
                    MMA(ar[nt], alf[ks], bh);
                    LDSM2(bh, ba + 16384);         // Ui hi
                    LDSM2(blo, ba + 24576);        // Ui lo
                    MMA(ai[nt], ahf[ks], bh);
                    MMA(ai[nt], ahf[ks], blo);
                    MMA(ai[nt], alf[ks], bh);
                }
            }
            // expvals from fragments: z = hf*32 + nt*8 + (lane&3)*2 + j
            #pragma unroll
            for (int nt = 0; nt < 4; nt++) {
                #pragma unroll
                for (int r2 = 0; r2 < 2; r2++) {
                    #pragma unroll
                    for (int j = 0; j < 2; j++) {
                        float rr = ar[nt][r2 * 2 + j], ii = ai[nt][r2 * 2 + j];
                        float p = rr * rr + ii * ii;
                        eacc[r2][0] += hf ? -p : p;
                        eacc[r2][1] += (nt & 2) ? -p : p;
                        eacc[r2][2] += (nt & 1) ? -p : p;
                        eacc[r2][3] = fmaf(s3, p, eacc[r2][3]);
                        eacc[r2][4] = fmaf(s4, p, eacc[r2][4]);
                        eacc[r2][5] += j ? -p : p;
                    }
                }
            }
        }
        #pragma unroll
        for (int r2 = 0; r2 < 2; r2++)
            #pragma unroll
            for (int i = 0; i < 6; i++) {
                eacc[r2][i] += __shfl_xor_sync(0xffffffffu, eacc[r2][i], 1);
                eacc[r2][i] += __shfl_xor_sync(0xffffffffu, eacc[r2][i], 2);
            }
        if ((lane & 3) == 0) {
            int p0r = (wid << 4) + (lane >> 2);
            #pragma unroll
            for (int i = 0; i < 6; i++) {
                e_s[p0r * 9 + i] = eacc[0][i];
                e_s[(p0r + 8) * 9 + i] = eacc[1][i];
            }
        }
    }
    __syncthreads();

    // --- Epilogue: 512 threads = (pixel, 8-ch group), 4 rows ---
    if (tid < 512) {
        const int wE  = tid & 63;
        const int cgE = tid >> 6;
        #pragma unroll
        for (int o2 = 0; o2 < 4; o2++) {
            float ev[6];
            #pragma unroll
            for (int i = 0; i < 6; i++) ev[i] = e_s[(o2 * 64 + wE) * 9 + i];
            #pragma unroll
            for (int j = 0; j < 8; j++) {
                int c = cgE * 8 + j;
                float v = conv_s[(o2 * 64 + wE) * 80 + c] + pob[c] + prb[c];
                #pragma unroll
                for (int i = 0; i < 6; i++) v += pw[c * 6 + i] * ev[i];
                out[((b * 64 + c) * 64 + (h0 + o2)) * 64 + wE] = v;
            }
        }
    }
}

// ---------------------------------------------------------------------------
extern "C" void kernel_launch(void* const* d_in, const int* in_sizes, int n_in,
                              void* d_out, int out_size)
{
    (void)in_sizes; (void)n_in; (void)out_size;
    const float* x      = (const float*)d_in[0];
    const float* style  = (const float*)d_in[1];
    const float* dat_w  = (const float*)d_in[2];
    const float* dat_b  = (const float*)d_in[3];
    const float* s2d_w  = (const float*)d_in[4];
    const float* s2d_b  = (const float*)d_in[5];
    const float* qcnn   = (const float*)d_in[6];
    const float* meas   = (const float*)d_in[7];
    const float* out_w  = (const float*)d_in[8];
    const float* out_b  = (const float*)d_in[9];
    const float* res_w  = (const float*)d_in[10];
    const float* res_b  = (const float*)d_in[11];
    float* out = (float*)d_out;

    cudaFuncSetAttribute(qcnn_main_kernel,
                         cudaFuncAttributeMaxDynamicSharedMemorySize, SMEM_BYTES);

    qcnn_setup_kernel<<<163, 256>>>(style, s2d_w, s2d_b, qcnn, meas, res_w, dat_w);
    qcnn_main_kernel<<<128, 640, SMEM_BYTES>>>(x, dat_b, out_w, out_b, res_b, out);
}

// round 16
// speedup vs baseline: 1.0390x; 1.0390x over previous
#include <cuda_runtime.h>
#include <cuda_bf16.h>
#include <math.h>
#include <stdint.h>

#define PI_F 3.14159265358979323846f
// B=8, C=64, H=W=64, K=3, PD=576, SD=128, NQ=6, NL=2

__device__ float g_style[48];
// Pre-swizzled B tiles: [9 shifts][hi 80x64 | lo 80x64] bf16, [n][k] rows,
// 16B chunk index ^= (n&7). 20480 B per shift.
__device__ __align__(16) unsigned short g_Bt[9][10240];
// U bf16 planes: [z][s] rows of 64 bf16 (128B), chunk ^= (z&7).
// plane 0 = Ur hi, 1 = Ur lo, 2 = Ui hi, 3 = Ui lo.
__device__ __align__(16) unsigned short g_Ubf[4][4096];

__device__ __forceinline__ uint32_t smem_u32(const void* p) {
    uint32_t a;
    asm("{ .reg .u64 t; cvta.to.shared.u64 t, %1; cvt.u32.u64 %0, t; }" : "=r"(a) : "l"(p));
    return a;
}
__device__ __forceinline__ float fast_tanh(float x) {
    float t = __expf(-2.f * fabsf(x));
    float r = __fdividef(1.f - t, 1.f + t);
    return (x < 0.f) ? -r : r;
}

#define LDSM4(r, a) asm volatile("ldmatrix.sync.aligned.m8n8.x4.shared.b16 {%0,%1,%2,%3}, [%4];" \
    : "=r"((r)[0]), "=r"((r)[1]), "=r"((r)[2]), "=r"((r)[3]) : "r"(a))
#define LDSM2(r, a) asm volatile("ldmatrix.sync.aligned.m8n8.x2.shared.b16 {%0,%1}, [%2];" \
    : "=r"((r)[0]), "=r"((r)[1]) : "r"(a))
#define MMA(d, a, bb2) asm volatile( \
    "mma.sync.aligned.m16n8k16.row.col.f32.bf16.bf16.f32 " \
    "{%0,%1,%2,%3}, {%4,%5,%6,%7}, {%8,%9}, {%0,%1,%2,%3};" \
    : "+f"((d)[0]), "+f"((d)[1]), "+f"((d)[2]), "+f"((d)[3]) \
    : "r"((a)[0]), "r"((a)[1]), "r"((a)[2]), "r"((a)[3]), "r"((bb2)[0]), "r"((bb2)[1]))

__device__ __forceinline__ uint32_t pack_bf2(float a0, float a1) {
    __nv_bfloat16 h0 = __float2bfloat16(a0);
    __nv_bfloat16 h1 = __float2bfloat16(a1);
    return ((uint32_t)__bfloat16_as_ushort(h1) << 16) | __bfloat16_as_ushort(h0);
}

// ---------------------------------------------------------------------------
// Merged setup kernel: blocks 0..179 build B tiles; block 180 runs the
// quantum circuit (style angles + U bf16 planes), all-MUFU transcendentals.
// ---------------------------------------------------------------------------
__global__ void qcnn_setup_kernel(const float* __restrict__ style,
                                  const float* __restrict__ s2d_w,
                                  const float* __restrict__ s2d_b,
                                  const float* __restrict__ qcnn,
                                  const float* __restrict__ meas,
                                  const float* __restrict__ res_w,
                                  const float* __restrict__ dat_w)
{
    const int tid = threadIdx.x;  // 0..255

    if (blockIdx.x < 180) {
        int idx = blockIdx.x * 256 + tid;
        if (idx >= 46080) return;
        int shift = idx / 5120;
        int rem = idx - shift * 5120;
        int n = rem >> 6, c = rem & 63;
        int dy = shift / 3, dx = shift - dy * 3;
        int k = c * 9 + dy * 3 + dx;
        float wv = 0.f;
        if (n < 64) wv = res_w[n * 576 + k];
        else if (n < 70) wv = dat_w[(n - 64) * 576 + k];
        __nv_bfloat16 hi = __float2bfloat16(wv);
        __nv_bfloat16 lo = __float2bfloat16(wv - __bfloat162float(hi));
        int us = (n << 6) + (((c >> 3) ^ (n & 7)) << 3) + (c & 7);
        ((__nv_bfloat16*)g_Bt[shift])[us] = hi;
        ((__nv_bfloat16*)g_Bt[shift])[us + 5120] = lo;
        return;
    }

    // ---- block 180: quantum circuit ----
    if (tid < 48) {
        int b = tid / 6, j = tid - 6 * b;
        float acc = s2d_b[j];
        const float* sp = style + b * 128;
        const float* wp = s2d_w + j * 128;
        #pragma unroll 8
        for (int k = 0; k < 128; k++) acc += sp[k] * wp[k];
        g_style[tid] = fast_tanh(acc) * PI_F;
    }

    const int c = tid >> 2;
    const int q = tid & 3;
    const unsigned FULL = 0xffffffffu;
    float ur[16], ui[16];
    #pragma unroll
    for (int zz = 0; zz < 16; zz++) { ur[zz] = (c == q * 16 + zz) ? 1.f : 0.f; ui[zz] = 0.f; }

    for (int l = 0; l < 2; l++) {
        #pragma unroll
        for (int i = 0; i < 6; i++) {
            const int m = 1 << (5 - i);
            float thy = qcnn[((l * 6 + i) * 2 + 0) * 3 + 0];
            float thz = qcnn[((l * 6 + i) * 2 + 1) * 3 + 0];
            float cy, sy; __sincosf(0.5f * thy, &sy, &cy);
            if (m < 16) {
                #pragma unroll
                for (int zz = 0; zz < 16; zz++) {
                    if (!(zz & m)) {
                        int z1 = zz | m;
                        float r0 = ur[zz], i0 = ui[zz], r1 = ur[z1], i1 = ui[z1];
                        ur[zz] = cy * r0 - sy * r1;  ui[zz] = cy * i0 - sy * i1;
                        ur[z1] = sy * r0 + cy * r1;  ui[z1] = sy * i0 + cy * i1;
                    }
                }
            } else {
                const int lane = m >> 4;
                const int bitv = (q * 16 & m) ? 1 : 0;
                #pragma unroll
                for (int zz = 0; zz < 16; zz++) {
                    float pr = __shfl_xor_sync(FULL, ur[zz], lane);
                    float pi = __shfl_xor_sync(FULL, ui[zz], lane);
                    if (bitv == 0) { ur[zz] = cy * ur[zz] - sy * pr; ui[zz] = cy * ui[zz] - sy * pi; }
                    else           { ur[zz] = sy * pr + cy * ur[zz]; ui[zz] = sy * pi + cy * ui[zz]; }
                }
            }
            float cz, sz; __sincosf(0.5f * thz, &sz, &cz);
            #pragma unroll
            for (int zz = 0; zz < 16; zz++) {
                int z = q * 16 + zz;
                float ph = (z & m) ? sz : -sz;
                float r = ur[zz], im = ui[zz];
                ur[zz] = cz * r - ph * im;
                ui[zz] = cz * im + ph * r;
            }
        }
        #pragma unroll
        for (int i = 0; i < 6; i++) {
            const int mc = 1 << (5 - i);
            const int mt = 1 << (5 - ((i + 1) % 6));
            if (mt < 16) {
                #pragma unroll
                for (int zz = 0; zz < 16; zz++) {
                    int z = q * 16 + zz;
                    if ((z & mc) && !(zz & mt)) {
                        int z2 = zz | mt;
                        float tr = ur[zz], ti = ui[zz];
                        ur[zz] = ur[z2];  ui[zz] = ui[z2];
                        ur[z2] = tr;      ui[z2] = ti;
                    }
                }
            } else {
                const int lane = mt >> 4;
                #pragma unroll
                for (int zz = 0; zz < 16; zz++) {
                    float pr = __shfl_xor_sync(FULL, ur[zz], lane);
                    float pi = __shfl_xor_sync(FULL, ui[zz], lane);
                    int z = q * 16 + zz;
                    if (z & mc) { ur[zz] = pr; ui[zz] = pi; }
                }
            }
        }
    }
    #pragma unroll
    for (int i = 0; i < 6; i++) {
        const int m = 1 << (5 - i);
        float th = meas[i * 3 + 0], ph = meas[i * 3 + 1], la = meas[i * 3 + 2];
        float ct, st; __sincosf(0.5f * th, &st, &ct);
        float cl, sl; __sincosf(la, &sl, &cl);
        float cp, sp; __sincosf(ph, &sp, &cp);
        float cpl, spl; __sincosf(ph + la, &spl, &cpl);
        float u01r = -cl * st, u01i = -sl * st;
        float u10r =  cp * st, u10i =  sp * st;
        float u11r = cpl * ct, u11i = spl * ct;
        if (m < 16) {
            #pragma unroll
            for (int zz = 0; zz < 16; zz++) {
                if (!(zz & m)) {
                    int z1 = zz | m;
                    float r0 = ur[zz], i0 = ui[zz], r1 = ur[z1], i1 = ui[z1];
                    ur[zz] = ct * r0 + u01r * r1 - u01i * i1;
                    ui[zz] = ct * i0 + u01r * i1 + u01i * r1;
                    ur[z1] = u10r * r0 - u10i * i0 + u11r * r1 - u11i * i1;
                    ui[z1] = u10r * i0 + u10i * r0 + u11r * i1 + u11i * r1;
                }
            }
        } else {
            const int lane = m >> 4;
            const int bitv = (q * 16 & m) ? 1 : 0;
            #pragma unroll
            for (int zz = 0; zz < 16; zz++) {
                float pr = __shfl_xor_sync(FULL, ur[zz], lane);
                float pi = __shfl_xor_sync(FULL, ui[zz], lane);
                float r0 = ur[zz], i0 = ui[zz];
                if (bitv == 0) {
                    ur[zz] = ct * r0 + u01r * pr - u01i * pi;
                    ui[zz] = ct * i0 + u01r * pi + u01i * pr;
                } else {
                    ur[zz] = u10r * pr - u10i * pi + u11r * r0 - u11i * i0;
                    ui[zz] = u10r * pi + u10i * pr + u11r * i0 + u11i * r0;
                }
            }
        }
    }
    // bf16 split planes, transposed to [z][s], ldmatrix-swizzled
    #pragma unroll
    for (int zz = 0; zz < 16; zz++) {
        int z = q * 16 + zz;
        int us = (z << 6) + (((c >> 3) ^ (z & 7)) << 3) + (c & 7);
        __nv_bfloat16 rh = __float2bfloat16(ur[zz]);
        __nv_bfloat16 rl = __float2bfloat16(ur[zz] - __bfloat162float(rh));
        __nv_bfloat16 ih = __float2bfloat16(ui[zz]);
        __nv_bfloat16 il = __float2bfloat16(ui[zz] - __bfloat162float(ih));
        ((__nv_bfloat16*)g_Ubf[0])[us] = rh;
        ((__nv_bfloat16*)g_Ubf[1])[us] = rl;
        ((__nv_bfloat16*)g_Ubf[2])[us] = ih;
        ((__nv_bfloat16*)g_Ubf[3])[us] = il;
    }
}

// ---------------------------------------------------------------------------
// Main kernel: 128 blocks x 640 threads (single wave). Block = (b, 4 rows).
// Conv AND quantum matvec on mma.sync m16n8k16 bf16 (3-term split each).
// SMEM (bytes):
//   XPH@0(50688) XPL@50688 | B0@101376(20480) B1@121856(20480)
//   UBF@147456 (32768)  e_s@180224(9216)
//   pw@189440(1536) pob@190976(256) prb@191232(256) pst@191488(64)
// Overlays (post-conv): conv_s@0 [4][64][80]f32 (81920),
//   a_hi@81920(32768), a_lo@114688(32768)
// ---------------------------------------------------------------------------
#define OFF_XPL  50688
#define OFF_B0   101376
#define OFF_AHI  81920
#define OFF_ALO  114688
#define OFF_UBF  147456
#define OFF_ES   180224
#define OFF_PW   189440
#define OFF_POB  190976
#define OFF_PRB  191232
#define OFF_PST  191488
#define SMEM_BYTES 191552

__global__ __launch_bounds__(640, 1)
void qcnn_main_kernel(const float* __restrict__ x,
                      const float* __restrict__ dat_b,
                      const float* __restrict__ out_w,
                      const float* __restrict__ out_b,
                      const float* __restrict__ res_b,
                      float* __restrict__ out)
{
    extern __shared__ char smc[];
    const uint32_t smem_base = smem_u32(smc);
    float* conv_s = (float*)smc;                 // overlay post-GEMM
    float* e_s    = (float*)(smc + OFF_ES);
    float* pw     = (float*)(smc + OFF_PW);
    float* pob    = (float*)(smc + OFF_POB);
    float* prb    = (float*)(smc + OFF_PRB);
    float* pst    = (float*)(smc + OFF_PST);

    const int tid  = threadIdx.x;
    const int wid  = tid >> 5;
    const int lane = tid & 31;
    const int b    = blockIdx.x >> 4;
    const int h0   = (blockIdx.x & 15) << 2;

    // --- conflict-free transpose staging of input hi/lo planes ---
    for (int t = wid; t < 96; t += 20) {
        const int r  = t >> 4;
        const int wh = (t >> 3) & 1;
        const int ch = t & 7;
        const int w  = wh * 32 + lane;    // padded w index 0..63
        const int gw = w - 1;
        const int hr = h0 + r - 1;
        const bool ok = (hr >= 0) && (hr < 64) && (gw >= 0);
        float v[8];
        #pragma unroll
        for (int c2 = 0; c2 < 8; c2++) {
            int cc = ch * 8 + c2;
            v[c2] = ok ? x[(((b * 64 + cc) * 64 + hr) << 6) + gw] : 0.f;
        }
        uint4 hi4, lo4;
        uint32_t* hp = (uint32_t*)&hi4;
        uint32_t* lp = (uint32_t*)&lo4;
        #pragma unroll
        for (int j = 0; j < 4; j++) {
            float a0 = v[2 * j], a1 = v[2 * j + 1];
            __nv_bfloat16 h0b = __float2bfloat16(a0);
            __nv_bfloat16 h1b = __float2bfloat16(a1);
            hp[j] = ((uint32_t)__bfloat16_as_ushort(h1b) << 16) | __bfloat16_as_ushort(h0b);
            lp[j] = pack_bf2(a0 - __bfloat162float(h0b), a1 - __bfloat162float(h1b));
        }
        const int addr = ((r * 66 + w) << 7) + ((ch ^ (w & 7)) << 4);
        *(uint4*)(smc + addr) = hi4;
        *(uint4*)(smc + OFF_XPL + addr) = lo4;
    }
    // edge columns w=64 (gw=63) and w=65 (pad)
    if (tid < 96) {
        const int r  = tid >> 4;
        const int rem = tid & 15;
        const int ch = rem >> 1;
        const int w  = 64 + (rem & 1);
        const int hr = h0 + r - 1;
        const bool ok = (w == 64) && (hr >= 0) && (hr < 64);
        uint4 hi4, lo4;
        uint32_t* hp = (uint32_t*)&hi4;
        uint32_t* lp = (uint32_t*)&lo4;
        #pragma unroll
        for (int j = 0; j < 4; j++) {
            float a0 = 0.f, a1 = 0.f;
            if (ok) {
                int cc = ch * 8 + 2 * j;
                a0 = x[(((b * 64 + cc) * 64 + hr) << 6) + 63];
                a1 = x[(((b * 64 + cc + 1) * 64 + hr) << 6) + 63];
            }
            __nv_bfloat16 h0b = __float2bfloat16(a0);
            __nv_bfloat16 h1b = __float2bfloat16(a1);
            hp[j] = ((uint32_t)__bfloat16_as_ushort(h1b) << 16) | __bfloat16_as_ushort(h0b);
            lp[j] = pack_bf2(a0 - __bfloat162float(h0b), a1 - __bfloat162float(h1b));
        }
        const int addr = ((r * 66 + w) << 7) + ((ch ^ (w & 7)) << 4);
        *(uint4*)(smc + addr) = hi4;
        *(uint4*)(smc + OFF_XPL + addr) = lo4;
    }
    // --- B shift 0 into buf 0 ---
    {
        const uint4* src = (const uint4*)(g_Bt[0]);
        uint4* dst = (uint4*)(smc + OFF_B0);
        for (int i = tid; i < 1280; i += 640) dst[i] = src[i];
    }

    // compute-warp geometry (conv)
    const int mt  = wid >> 1;
    const int nh  = wid & 1;
    const int o   = mt >> 1;
    const int w0c = (mt & 1) * 32;
    const int n0  = nh * 40;
    const int l15 = lane & 15;
    const int bln = lane & 7;
    const uint32_t brow = (uint32_t)(n0 + bln) * 128;

    float acc[2][5][4];
    #pragma unroll
    for (int m = 0; m < 2; m++)
        #pragma unroll
        for (int nt = 0; nt < 5; nt++)
            #pragma unroll
            for (int j = 0; j < 4; j++) acc[m][nt][j] = 0.f;

    for (int st = 0; st < 9; st++) {
        __syncthreads();
        const uint32_t bb = smem_base + OFF_B0 + (uint32_t)(st & 1) * 20480;
        if (wid < 16) {
            const int dy = st / 3, dx = st - dy * 3;
            const int srow = o + dy;
            const int ws0 = w0c + l15 + dx;
            const int ws1 = ws0 + 16;
            const uint32_t arow0 = (uint32_t)((srow * 66 + ws0) << 7);
            const uint32_t arow1 = (uint32_t)((srow * 66 + ws1) << 7);
            const uint32_t sw0 = ws0 & 7, sw1 = ws1 & 7;
            const uint32_t xb = smem_base;
            #pragma unroll
            for (int k0 = 0; k0 < 64; k0 += 16) {
                const uint32_t kca = (uint32_t)(k0 >> 3) + (uint32_t)(lane >> 4);
                uint32_t ah0[4], ah1[4], al0[4], al1[4], bf[5][2];
                uint32_t ad0 = xb + arow0 + ((kca ^ sw0) << 4);
                uint32_t ad1 = xb + arow1 + ((kca ^ sw1) << 4);
                LDSM4(ah0, ad0);
                LDSM4(ah1, ad1);
                LDSM4(al0, ad0 + OFF_XPL);
                LDSM4(al1, ad1 + OFF_XPL);
                const uint32_t kcb = (uint32_t)(k0 >> 3) + (uint32_t)((lane >> 3) & 1);
                const uint32_t boff = bb + brow + ((kcb ^ (uint32_t)bln) << 4);
                #pragma unroll
                for (int nt = 0; nt < 5; nt++) LDSM2(bf[nt], boff + nt * 1024);
                #pragma unroll
                for (int nt = 0; nt < 5; nt++) { MMA(acc[0][nt], ah0, bf[nt]); MMA(acc[1][nt], ah1, bf[nt]); }
                #pragma unroll
                for (int nt = 0; nt < 5; nt++) { MMA(acc[0][nt], al0, bf[nt]); MMA(acc[1][nt], al1, bf[nt]); }
                #pragma unroll
                for (int nt = 0; nt < 5; nt++) LDSM2(bf[nt], boff + nt * 1024 + 10240);
                #pragma unroll
                for (int nt = 0; nt < 5; nt++) { MMA(acc[0][nt], ah0, bf[nt]); MMA(acc[1][nt], ah1, bf[nt]); }
            }
        } else {
            const int t2 = tid - 512;
            if (st < 8) {
                const uint4* src = (const uint4*)(g_Bt[st + 1]);
                uint4* dst = (uint4*)(smc + OFF_B0 + ((st + 1) & 1) * 20480);
                #pragma unroll
                for (int i = 0; i < 10; i++) dst[t2 + i * 128] = src[t2 + i * 128];
            }
            if (st >= 1 && st <= 4) {   // spread UBF staging across stages 1-4
                const int base = (st - 1) * 512;
                #pragma unroll
                for (int i = 0; i < 4; i++)
                    ((uint4*)(smc + OFF_UBF))[base + t2 + i * 128] =
                        ((const uint4*)g_Ubf)[base + t2 + i * 128];
            }
            if (st == 0) {  // params + style
                if (t2 < 96) ((uint4*)pw)[t2] = ((const uint4*)out_w)[t2];
                else if (t2 < 112) ((uint4*)pob)[t2 - 96] = ((const uint4*)out_b)[t2 - 96];
                else if (t2 < 128) ((uint4*)prb)[t2 - 112] = ((const uint4*)res_b)[t2 - 112];
                if (t2 < 6) { pst[t2] = g_style[b * 6 + t2]; pst[8 + t2] = dat_b[t2]; }
            }
        }
    }
    __syncthreads();   // all XP/B readers done -> safe to overlay conv_s

    // --- writeout conv acc -> conv_s [o][w][80] ---
    if (wid < 16) {
        const int r0 = lane >> 2;
        const int nc = n0 + (lane & 3) * 2;
        #pragma unroll
        for (int m = 0; m < 2; m++) {
            const int wpx = w0c + m * 16 + r0;
            #pragma unroll
            for (int nt = 0; nt < 5; nt++) {
                *(float2*)&conv_s[(o * 64 + wpx) * 80 + nc + nt * 8] =
                    make_float2(acc[m][nt][0], acc[m][nt][1]);
                *(float2*)&conv_s[(o * 64 + wpx + 8) * 80 + nc + nt * 8] =
                    make_float2(acc[m][nt][2], acc[m][nt][3]);
            }
        }
    }
    __syncthreads();

    // --- build product-state a as bf16 hi/lo planes [p(256)][s(64)] ---
    if (tid < 512) {
        const int q  = tid & 3;
        const int p2 = tid >> 2;
        #pragma unroll
        for (int it = 0; it < 2; it++) {
            const int p  = it * 128 + p2;
            const int o2 = p >> 6;
            const int wq = p & 63;
            float cc6[6], sn6[6];
            #pragma unroll
            for (int i = 0; i < 6; i++) {
                float pre = conv_s[(o2 * 64 + wq) * 80 + 64 + i];
                float th = fast_tanh(pre + pst[8 + i]) * PI_F + pst[i];
                __sincosf(0.5f * th, &sn6[i], &cc6[i]);
            }
            char* ah = smc + OFF_AHI + (p << 7);
            char* al = smc + OFF_ALO + (p << 7);
            const int psw = p & 7;
            #pragma unroll
            for (int zz = 0; zz < 16; zz += 2) {
                int s = q * 16 + zz;
                float a0 = ((s >> 5) & 1) ? sn6[0] : cc6[0];
                float a1 = (((s + 1) >> 5) & 1) ? sn6[0] : cc6[0];
                #pragma unroll
                for (int i = 1; i < 6; i++) {
                    a0 *= ((s >> (5 - i)) & 1) ? sn6[i] : cc6[i];
                    a1 *= (((s + 1) >> (5 - i)) & 1) ? sn6[i] : cc6[i];
                }
                __nv_bfloat16 h0 = __float2bfloat16(a0);
                __nv_bfloat16 h1 = __float2bfloat16(a1);
                uint32_t vh = ((uint32_t)__bfloat16_as_ushort(h1) << 16) | __bfloat16_as_ushort(h0);
                uint32_t vl = pack_bf2(a0 - __bfloat162float(h0), a1 - __bfloat162float(h1));
                int off = ((((s >> 3)) ^ psw) << 4) + ((s & 7) << 1);
                *(uint32_t*)(ah + off) = vh;
                *(uint32_t*)(al + off) = vl;
            }
        }
    }
    __syncthreads();

    // --- quantum matvec on HMMA: psi[256][64] = a @ U (re + im) ---
    if (wid < 16) {
        const uint32_t abase = smem_base + OFF_AHI;
        const uint32_t ubf   = smem_base + OFF_UBF;
        const int prow = (wid << 4) + l15;
        uint32_t ahf[4][4], alf[4][4];
        #pragma unroll
        for (int ks = 0; ks < 4; ks++) {
            uint32_t kca = (uint32_t)(ks * 2) + (uint32_t)(lane >> 4);
            uint32_t ad = abase + (prow << 7) + ((kca ^ (uint32_t)(l15 & 7)) << 4);
            LDSM4(ahf[ks], ad);
            LDSM4(alf[ks], ad + 32768);
        }
        const int bl2 = lane & 7;
        const int bsel = (lane >> 3) & 1;
        const float s3 = (lane & 2) ? -1.f : 1.f;
        const float s4 = (lane & 1) ? -1.f : 1.f;
        float eacc[2][6];
        #pragma unroll
        for (int r2 = 0; r2 < 2; r2++)
            #pragma unroll
            for (int i = 0; i < 6; i++) eacc[r2][i] = 0.f;

        #pragma unroll
        for (int hf = 0; hf < 2; hf++) {
            float ar[4][4], ai[4][4];
            #pragma unroll
            for (int nt = 0; nt < 4; nt++)
                #pragma unroll
                for (int j = 0; j < 4; j++) { ar[nt][j] = 0.f; ai[nt][j] = 0.f; }
            #pragma unroll
            for (int nt = 0; nt < 4; nt++) {
                const int z0 = hf * 32 + nt * 8;
                const uint32_t brow2 = ubf + (uint32_t)((z0 + bl2) << 7);
                #pragma unroll
                for (int ks = 0; ks < 4; ks++) {
                    uint32_t bh[2], blo[2];
                    uint32_t ba = brow2 + ((((uint32_t)(ks * 2 + bsel)) ^ (uint32_t)bl2) << 4);
                    LDSM2(bh, ba);                 // Ur hi
                    LDSM2(blo, ba + 8192);         // Ur lo
                    MMA(ar[nt], ahf[ks], bh);
                    MMA(ar[nt], ahf[ks], blo);
                    MMA(ar[nt], alf[ks], bh);
                    LDSM2(bh, ba + 16384);         // Ui hi
                    LDSM2(blo, ba + 24576);        // Ui lo
                    MMA(ai[nt], ahf[ks], bh);
                    MMA(ai[nt], ahf[ks], blo);
                    MMA(ai[nt], alf[ks], bh);
                }
            }
            // expvals from fragments: z = hf*32 + nt*8 + (lane&3)*2 + j
            #pragma unroll
            for (int nt = 0; nt < 4; nt++) {
                #pragma unroll
                for (int r2 = 0; r2 < 2; r2++) {
                    #pragma unroll
                    for (int j = 0; j < 2; j++) {
                        float rr = ar[nt][r2 * 2 + j], ii = ai[nt][r2 * 2 + j];
                        float p = rr * rr + ii * ii;
                        eacc[r2][0] += hf ? -p : p;
                        eacc[r2][1] += (nt & 2) ? -p : p;
                        eacc[r2][2] += (nt & 1) ? -p : p;
                        eacc[r2][3] = fmaf(s3, p, eacc[r2][3]);
                        eacc[r2][4] = fmaf(s4, p, eacc[r2][4]);
                        eacc[r2][5] += j ? -p : p;
                    }
                }
            }
        }
        #pragma unroll
        for (int r2 = 0; r2 < 2; r2++)
            #pragma unroll
            for (int i = 0; i < 6; i++) {
                eacc[r2][i] += __shfl_xor_sync(0xffffffffu, eacc[r2][i], 1);
                eacc[r2][i] += __shfl_xor_sync(0xffffffffu, eacc[r2][i], 2);
            }
        if ((lane & 3) == 0) {
            int p0r = (wid << 4) + (lane >> 2);
            #pragma unroll
            for (int i = 0; i < 6; i++) {
                e_s[p0r * 9 + i] = eacc[0][i];
                e_s[(p0r + 8) * 9 + i] = eacc[1][i];
            }
        }
    }
    __syncthreads();

    // --- Epilogue: 512 threads = (pixel, 8-ch group), 4 rows ---
    if (tid < 512) {
        const int wE  = tid & 63;
        const int cgE = tid >> 6;
        #pragma unroll
        for (int o2 = 0; o2 < 4; o2++) {
            float ev[6];
            #pragma unroll
            for (int i = 0; i < 6; i++) ev[i] = e_s[(o2 * 64 + wE) * 9 + i];
            #pragma unroll
            for (int j = 0; j < 8; j++) {
                int c = cgE * 8 + j;
                float v = conv_s[(o2 * 64 + wE) * 80 + c] + pob[c] + prb[c];
                #pragma unroll
                for (int i = 0; i < 6; i++) v += pw[c * 6 + i] * ev[i];
                out[((b * 64 + c) * 64 + (h0 + o2)) * 64 + wE] = v;
            }
        }
    }
}

// ---------------------------------------------------------------------------
extern "C" void kernel_launch(void* const* d_in, const int* in_sizes, int n_in,
                              void* d_out, int out_size)
{
    (void)in_sizes; (void)n_in; (void)out_size;
    const float* x      = (const float*)d_in[0];
    const float* style  = (const float*)d_in[1];
    const float* dat_w  = (const float*)d_in[2];
    const float* dat_b  = (const float*)d_in[3];
    const float* s2d_w  = (const float*)d_in[4];
    const float* s2d_b  = (const float*)d_in[5];
    const float* qcnn   = (const float*)d_in[6];
    const float* meas   = (const float*)d_in[7];
    const float* out_w  = (const float*)d_in[8];
    const float* out_b  = (const float*)d_in[9];
    const float* res_w  = (const float*)d_in[10];
    const float* res_b  = (const float*)d_in[11];
    float* out = (float*)d_out;

    cudaFuncSetAttribute(qcnn_main_kernel,
                         cudaFuncAttributeMaxDynamicSharedMemorySize, SMEM_BYTES);

    qcnn_setup_kernel<<<181, 256>>>(style, s2d_w, s2d_b, qcnn, meas, res_w, dat_w);
    qcnn_main_kernel<<<128, 640, SMEM_BYTES>>>(x, dat_b, out_w, out_b, res_b, out);
}